// round 10
// baseline (speedup 1.0000x reference)
#include <cuda_runtime.h>

#define Bn 16
#define Tn 192
#define Un 64
#define Hn 512
#define NEGF (-1e30f)
#define LOG2E 1.4426950408889634f
#define LN2f  0.6931471805599453f

// Diagonal-major fused table, base-2 log domain.
// Cell (t,u) lives at row d = t+u, col u, as float2:
//   .x = lpb2[t-1][u], .y = lpl2[t][u-1]. OOR cells = NEGF (written by t==0 blocks).
__device__ float g_cd[Bn * 256 * Un * 2];
// Per-(b,t) completion counters (64 u-warps each). Reset in-kernel for graph replay.
__device__ int g_cnt[Bn * Tn];

__device__ __forceinline__ float warpMax(float v) {
#pragma unroll
    for (int o = 16; o > 0; o >>= 1)
        v = fmaxf(v, __shfl_xor_sync(0xffffffffu, v, o));
    return v;
}
__device__ __forceinline__ float warpSum(float v) {
#pragma unroll
    for (int o = 16; o > 0; o >>= 1)
        v += __shfl_xor_sync(0xffffffffu, v, o);
    return v;
}
__device__ __forceinline__ float ex2f(float x) {
    float r; asm("ex2.approx.ftz.f32 %0, %1;" : "=f"(r) : "f"(x)); return r;
}
__device__ __forceinline__ float lg2f(float x) {
    float r; asm("lg2.approx.ftz.f32 %0, %1;" : "=f"(r) : "f"(x)); return r;
}
__device__ __forceinline__ float laddexp2(float a, float b) {
    float m = fmaxf(a, b);
    float t = ex2f(-fabsf(a - b));
    return m + lg2f(1.0f + t);
}
// LDS.128 via asm volatile: not hoistable above the volatile flag-poll loop.
__device__ __forceinline__ float4 lds128v(const float* p) {
    float4 v; unsigned a = (unsigned)__cvta_generic_to_shared(p);
    asm volatile("ld.shared.v4.f32 {%0,%1,%2,%3}, [%4];"
                 : "=f"(v.x), "=f"(v.y), "=f"(v.z), "=f"(v.w) : "r"(a));
    return v;
}
__device__ __forceinline__ float extract_elem(
    const float4& v0, const float4& v1, const float4& v2, const float4& v3, int e) {
    int g = (e >> 7) & 3;
    int comp = e & 3;
    int srclane = (e >> 2) & 31;
    float4 vv = (g == 0) ? v0 : (g == 1) ? v1 : (g == 2) ? v2 : v3;
    float c = (comp == 0) ? vv.x : (comp == 1) ? vv.y : (comp == 2) ? vv.z : vv.w;
    return __shfl_sync(0xffffffffu, c, srclane);
}

#define SM_RING_F   (64 * Un * 2)              /* 8192 floats = 32 KB ring   */
#define SMEM_BYTES  (SM_RING_F * 4 + 258 * 4)  /* + flags[256] + W + cons    */

__global__ __launch_bounds__(512, 4)
void k_fused(const float* __restrict__ x,
             const int* __restrict__ label,
             const int* __restrict__ f_len,
             const int* __restrict__ y_len,
             const int* __restrict__ blankp,
             float* __restrict__ out) {
    extern __shared__ float sm[];
    float* ring = sm;                                  // 64 rows x 512 B
    int* s_flag = (int*)(sm + SM_RING_F);              // [256]
    volatile int* s_W    = (volatile int*)(s_flag + 256);
    volatile int* s_cons = (volatile int*)(s_flag + 257);

    const int bid = blockIdx.x;
    const int tid = threadIdx.x;
    const int warp = tid >> 5;
    const int lane = tid & 31;

    if (bid >= Bn) {
        // ================= LSE role =================
        const int bid2 = bid - Bn;
        const int q = bid2 & 3;
        const int b = (bid2 >> 2) & 15;
        const int t = bid2 >> 6;                       // t-major in time
        const int bt = b * Tn + t;
        const int u = (q << 4) + warp;                 // 0..63
        const int blank = blankp ? __ldg(blankp) : 0;

        float* const base = g_cd + (size_t)b * 256 * Un * 2;

        // NEGF init of unwritten cells (t==0 blocks only; disjoint writes)
        if (t == 0) {
#pragma unroll
            for (int h = 0; h < 2; h++) {
                int rr = lane + h * 32;                    // 0..63
                int rx = (rr <= u) ? rr : rr + 192;        // .x unwritten rows
                base[(rx * Un + u) * 2 + 0] = NEGF;
                if (u >= 1) {
                    int ry = (rr < u) ? rr : rr + 192;     // .y unwritten rows
                    base[(ry * Un + u) * 2 + 1] = NEGF;
                }
            }
            if (u == 0) {
#pragma unroll
                for (int h = 0; h < 8; h++)                // col 0 .y: all rows
                    base[((lane + h * 32) * Un) * 2 + 1] = NEGF;
            }
        }

        const float4* r = reinterpret_cast<const float4*>(x)
                          + ((size_t)bt * Un + u) * (Hn / 4);
        float4 a0 = __ldcs(r + lane);
        float4 a1 = __ldcs(r + lane + 32);
        float4 a2 = __ldcs(r + lane + 64);
        float4 a3 = __ldcs(r + lane + 96);

        int lab = (u < Un - 1) ? __ldg(&label[b * (Un - 1) + u]) : 0;

        float m = fmaxf(fmaxf(fmaxf(a0.x, a0.y), fmaxf(a0.z, a0.w)),
                 fmaxf(fmaxf(fmaxf(a1.x, a1.y), fmaxf(a1.z, a1.w)),
                 fmaxf(fmaxf(fmaxf(a2.x, a2.y), fmaxf(a2.z, a2.w)),
                       fmaxf(fmaxf(a3.x, a3.y), fmaxf(a3.z, a3.w)))));
        m = warpMax(m);
        float s = __expf(a0.x - m) + __expf(a0.y - m) + __expf(a0.z - m) + __expf(a0.w - m)
                + __expf(a1.x - m) + __expf(a1.y - m) + __expf(a1.z - m) + __expf(a1.w - m)
                + __expf(a2.x - m) + __expf(a2.y - m) + __expf(a2.z - m) + __expf(a2.w - m)
                + __expf(a3.x - m) + __expf(a3.y - m) + __expf(a3.z - m) + __expf(a3.w - m);
        s = warpSum(s);
        float denom = m + __logf(s);

        float xb = extract_elem(a0, a1, a2, a3, blank);
        float xl = extract_elem(a0, a1, a2, a3, lab);
        if (lane == 0) {
            base[(((t + u + 1) * Un) + u) * 2 + 0] = (xb - denom) * LOG2E;
            if (u < Un - 1)
                base[(((t + u + 1) * Un) + u + 1) * 2 + 1] = (xl - denom) * LOG2E;
        }
        // release: this warp's (and its guard) writes -> counter
        __syncwarp();
        if (lane == 0) {
            __threadfence();
            atomicAdd(&g_cnt[bt], 1);
        }
        return;
    }

    // ================= ALPHA role (b = bid) =================
    const int b = bid;
    if (tid < 256) s_flag[tid] = 0;
    if (tid == 256) *s_W = -1;
    if (tid == 257) *s_cons = 0;
    __syncthreads();

    const float* gb = g_cd + (size_t)b * 256 * Un * 2;

    if (warp == 9) {
        // scanner: contiguous watermark over g_cnt[b][0..191], then reset counters
        int* cb = g_cnt + b * Tn;
        int W = -1;
        while (W < Tn - 1) {
            int idx = W + 1 + lane;
            int done = (idx < Tn) ? ((*(volatile int*)(cb + idx)) == 64) : 1;
            unsigned mk = __ballot_sync(0xffffffffu, done);
            int adv = __ffs(~mk) - 1;
            if (adv < 0) adv = 32;
            if (adv == 0) { __nanosleep(200); continue; }
            W += adv;
            __threadfence();                       // cumulative acquire before publish
            if (lane == 0) *s_W = W;
        }
        for (int i = lane; i < Tn; i += 32) cb[i] = 0;   // reset for next replay
        return;
    }
    if (warp >= 1 && warp <= 8) {
        // copier: rows r = (warp-1) + 8k into ring slot r & 63
#pragma unroll 1
        for (int k = 0; k < 32; k++) {
            int rr = (warp - 1) + (k << 3);
            int need = min(rr, Tn - 1);
            while (*s_W < need) __nanosleep(100);
            while (rr - 63 > *s_cons) __nanosleep(100);
            __threadfence_block();
            float4 v = *((const float4*)(gb + rr * (Un * 2)) + lane);
            *((float4*)(ring + (rr & 63) * (Un * 2)) + lane) = v;
            __threadfence_block();
            __syncwarp();
            if (lane == 0) *(volatile int*)(s_flag + rr) = 1;
        }
        return;
    }
    if (warp != 0) return;

    // consumer (warp 0): wavefront, 2 u-cells/lane, flag-gated ring reads
    const int tl = f_len[b] - 1;                 // 95..191
    const int ul = y_len[b];                     // 32..63
    const int dHit = tl + ul;                    // <= 254
    const unsigned FULL = 0xffffffffu;

    while (*(volatile int*)(s_flag + 1) == 0) __nanosleep(50);
    float4 c = lds128v(ring + (1 & 63) * (Un * 2) + lane * 4);
    float aA = 0.f, aB = 0.f;                    // lane0: alpha2[0][0] = 0

#pragma unroll 2
    for (int d = 1; d <= dHit; d++) {
        while (*(volatile int*)(s_flag + d + 1) == 0) __nanosleep(50);
        float4 cn = lds128v(ring + ((d + 1) & 63) * (Un * 2) + lane * 4);
        float lA = __shfl_up_sync(FULL, aB, 1);  // lane0: dead (c.y == NEGF)
        float lB = aA;
        float nA = laddexp2(aA + c.x, lA + c.y);
        float nB = laddexp2(aB + c.z, lB + c.w);
        aA = nA;
        aB = nB;
        c = cn;
        if (((d & 15) == 0) && lane == 0) *s_cons = d;
    }

    if (lane == 0) *s_cons = 255;                // release copiers (exit)
    if (lane == (ul >> 1)) {
        float v  = (ul & 1) ? aB : aA;
        float fb = (ul & 1) ? c.z : c.x;         // c == row dHit+1: lpb2[tl][ul]
        out[b] = -(v + fb) * LN2f;
    }
}

extern "C" void kernel_launch(void* const* d_in, const int* in_sizes, int n_in,
                              void* d_out, int out_size) {
    const float* x = (const float*)d_in[0];
    const int* label = (const int*)d_in[1];
    const int* f_len = (const int*)d_in[2];
    const int* y_len = (const int*)d_in[3];
    const int* blankp = (n_in > 4) ? (const int*)d_in[4] : nullptr;

    cudaFuncSetAttribute(k_fused, cudaFuncAttributeMaxDynamicSharedMemorySize,
                         SMEM_BYTES);
    k_fused<<<Bn + Bn * Tn * 4, 512, SMEM_BYTES>>>(x, label, f_len, y_len,
                                                   blankp, (float*)d_out);
}